// round 1
// baseline (speedup 1.0000x reference)
#include <cuda_runtime.h>

#define N_NODES 50000
#define E_EDGES 800000
#define IN_DIM  128
#define H_DIM   96
#define OUT_DIM 64
#define NUM_LAYERS 4

// ---------------- static device scratch (no allocations allowed) ----------------
__device__ float  g_h0[N_NODES * H_DIM];
__device__ float  g_h1[N_NODES * H_DIM];
__device__ float  g_m[(size_t)N_NODES * 2 * H_DIM];        // [node][head*96+d], row = 192 floats
__device__ int    g_counts[N_NODES];
__device__ int    g_offsets[N_NODES + 1];
__device__ int    g_cursor[N_NODES];
__device__ int    g_src_sorted[E_EDGES];
__device__ float2 g_ews[NUM_LAYERS][E_EDGES];              // per-layer (ew_h0, ew_h1) in dst-sorted order
__device__ float  g_zero_bias[H_DIM];                      // zero-initialized (static storage)

// ---------------- CSR build ----------------
__global__ void zero_counts_kernel() {
    int i = blockIdx.x * blockDim.x + threadIdx.x;
    if (i < N_NODES) g_counts[i] = 0;
}

__global__ void hist_kernel(const int* __restrict__ dst) {
    int e = blockIdx.x * blockDim.x + threadIdx.x;
    if (e < E_EDGES) atomicAdd(&g_counts[dst[e]], 1);
}

// single-block exclusive scan over 50000 counters
__global__ void scan_kernel() {
    __shared__ int sh[1024];
    __shared__ int carry;
    int t = threadIdx.x;
    if (t == 0) carry = 0;
    __syncthreads();
    for (int base = 0; base < N_NODES; base += 1024) {
        int i = base + t;
        int v = (i < N_NODES) ? g_counts[i] : 0;
        sh[t] = v;
        __syncthreads();
        for (int off = 1; off < 1024; off <<= 1) {
            int x = (t >= off) ? sh[t - off] : 0;
            __syncthreads();
            sh[t] += x;
            __syncthreads();
        }
        int excl = carry + sh[t] - v;   // reads old carry
        if (i < N_NODES) { g_offsets[i] = excl; g_cursor[i] = excl; }
        __syncthreads();
        if (t == 1023) carry += sh[1023];
        __syncthreads();
    }
    if (t == 0) g_offsets[N_NODES] = carry;
}

__global__ void scatter_kernel(const int* __restrict__ src,
                               const int* __restrict__ dst,
                               const float* __restrict__ conv_ew) {
    int e = blockIdx.x * blockDim.x + threadIdx.x;
    if (e >= E_EDGES) return;
    int d = dst[e];
    int pos = atomicAdd(&g_cursor[d], 1);
    g_src_sorted[pos] = src[e];
    #pragma unroll
    for (int l = 0; l < NUM_LAYERS; l++) {
        float w0 = conv_ew[(size_t)(l * 2 + 0) * E_EDGES + e];
        float w1 = conv_ew[(size_t)(l * 2 + 1) * E_EDGES + e];
        g_ews[l][pos] = make_float2(w0, w1);
    }
}

// ---------------- register-tiled fp32 GEMM ----------------
// C rows stride ldc, cols [colOff, colOff+TN*16) = A[M x K] * B[K x TN*16] + bias, optional relu
template <int TN, bool RELU>
__global__ void gemm_kernel(const float* __restrict__ A, const float* __restrict__ B,
                            const float* __restrict__ bias, float* __restrict__ C,
                            int M, int K, int lda, int ldb, int ldc, int colOff) {
    constexpr int BN = TN * 16;
    constexpr int BM = 64;
    constexpr int BK = 32;
    constexpr int TM = 4;
    __shared__ float As[BK][BM + 1];
    __shared__ float Bs[BK][BN];

    int tid = threadIdx.x;
    int tx = tid & 15;
    int ty = tid >> 4;
    int blockRow = blockIdx.x * BM;

    float acc[TM][TN];
    #pragma unroll
    for (int i = 0; i < TM; i++)
        #pragma unroll
        for (int j = 0; j < TN; j++) acc[i][j] = 0.f;

    for (int k0 = 0; k0 < K; k0 += BK) {
        #pragma unroll
        for (int r = 0; r < (BM * BK) / 256; r++) {
            int e = tid + r * 256;
            int row = e >> 5;
            int col = e & 31;
            int gRow = blockRow + row;
            As[col][row] = (gRow < M) ? A[(size_t)gRow * lda + k0 + col] : 0.f;
        }
        #pragma unroll
        for (int r = 0; r < (BK * BN) / 256; r++) {
            int e = tid + r * 256;
            int row = e / BN;
            int col = e % BN;
            Bs[row][col] = B[(size_t)(k0 + row) * ldb + col];
        }
        __syncthreads();
        #pragma unroll
        for (int kk = 0; kk < BK; kk++) {
            float a[TM], b[TN];
            #pragma unroll
            for (int i = 0; i < TM; i++) a[i] = As[kk][ty * TM + i];
            #pragma unroll
            for (int j = 0; j < TN; j++) b[j] = Bs[kk][tx * TN + j];
            #pragma unroll
            for (int i = 0; i < TM; i++)
                #pragma unroll
                for (int j = 0; j < TN; j++) acc[i][j] += a[i] * b[j];
        }
        __syncthreads();
    }

    #pragma unroll
    for (int i = 0; i < TM; i++) {
        int gRow = blockRow + ty * TM + i;
        if (gRow >= M) continue;
        #pragma unroll
        for (int j = 0; j < TN; j++) {
            int c = tx * TN + j;
            float v = acc[i][j] + bias[c];
            if (RELU) v = fmaxf(v, 0.f);
            C[(size_t)gRow * ldc + colOff + c] = v;
        }
    }
}

// ---------------- per-node aggregation (warp per node) ----------------
__global__ void aggregate_kernel(const float* __restrict__ m, int layer,
                                 float* __restrict__ hout) {
    int warp = (blockIdx.x * blockDim.x + threadIdx.x) >> 5;
    int lane = threadIdx.x & 31;
    if (warp >= N_NODES) return;
    int beg = g_offsets[warp];
    int end = g_offsets[warp + 1];
    const float2* __restrict__ ews = g_ews[layer];

    float acc0 = 0.f, acc1 = 0.f, acc2 = 0.f;
    int j = beg;
    for (; j + 1 < end; j += 2) {
        int s0 = g_src_sorted[j];
        int s1 = g_src_sorted[j + 1];
        float2 w0 = ews[j];
        float2 w1 = ews[j + 1];
        const float* r0 = m + (size_t)s0 * 192;
        const float* r1 = m + (size_t)s1 * 192;
        float a0 = r0[lane],      b0 = r0[96 + lane];
        float a1 = r0[32 + lane], b1 = r0[128 + lane];
        float a2 = r0[64 + lane], b2 = r0[160 + lane];
        float c0 = r1[lane],      d0 = r1[96 + lane];
        float c1 = r1[32 + lane], d1 = r1[128 + lane];
        float c2 = r1[64 + lane], d2 = r1[160 + lane];
        acc0 += w0.x * a0 + w0.y * b0;
        acc1 += w0.x * a1 + w0.y * b1;
        acc2 += w0.x * a2 + w0.y * b2;
        acc0 += w1.x * c0 + w1.y * d0;
        acc1 += w1.x * c1 + w1.y * d1;
        acc2 += w1.x * c2 + w1.y * d2;
    }
    if (j < end) {
        int s = g_src_sorted[j];
        float2 w = ews[j];
        const float* r = m + (size_t)s * 192;
        acc0 += w.x * r[lane]      + w.y * r[96 + lane];
        acc1 += w.x * r[32 + lane] + w.y * r[128 + lane];
        acc2 += w.x * r[64 + lane] + w.y * r[160 + lane];
    }
    float* o = hout + (size_t)warp * H_DIM;
    o[lane]      = fmaxf(acc0, 0.f);
    o[lane + 32] = fmaxf(acc1, 0.f);
    o[lane + 64] = fmaxf(acc2, 0.f);
}

__global__ void copy_h_kernel(const float* __restrict__ h, float* __restrict__ out) {
    int i = blockIdx.x * blockDim.x + threadIdx.x;
    if (i < N_NODES * H_DIM) out[i] = h[i];
}

// ---------------- launch ----------------
extern "C" void kernel_launch(void* const* d_in, const int* in_sizes, int n_in,
                              void* d_out, int out_size) {
    const float* x       = (const float*)d_in[0];
    const int*   eidx    = (const int*)d_in[1];
    const float* enc_w   = (const float*)d_in[2];
    const float* enc_b   = (const float*)d_in[3];
    const float* dec_w   = (const float*)d_in[4];
    const float* dec_b   = (const float*)d_in[5];
    const float* conv_W  = (const float*)d_in[6];
    const float* conv_ew = (const float*)d_in[7];
    float* out = (float*)d_out;

    const int* src = eidx;
    const int* dst = eidx + E_EDGES;

    void *p_h0, *p_h1, *p_m, *p_zb;
    cudaGetSymbolAddress(&p_h0, g_h0);
    cudaGetSymbolAddress(&p_h1, g_h1);
    cudaGetSymbolAddress(&p_m, g_m);
    cudaGetSymbolAddress(&p_zb, g_zero_bias);
    float* h0 = (float*)p_h0;
    float* h1 = (float*)p_h1;
    float* m  = (float*)p_m;
    const float* zb = (const float*)p_zb;

    // CSR build (per launch; deterministic work)
    zero_counts_kernel<<<(N_NODES + 255) / 256, 256>>>();
    hist_kernel<<<(E_EDGES + 255) / 256, 256>>>(dst);
    scan_kernel<<<1, 1024>>>();
    scatter_kernel<<<(E_EDGES + 255) / 256, 256>>>(src, dst, conv_ew);

    int gemmGrid = (N_NODES + 63) / 64;

    // encoder: h0 = relu(x @ enc_w + enc_b)
    gemm_kernel<6, true><<<gemmGrid, 256>>>(x, enc_w, enc_b, h0,
                                            N_NODES, IN_DIM, IN_DIM, H_DIM, H_DIM, 0);

    float* hin = h0;
    float* hout = h1;
    for (int l = 0; l < NUM_LAYERS; l++) {
        const float* W0 = conv_W + (size_t)(l * 2 + 0) * H_DIM * H_DIM;
        const float* W1 = conv_W + (size_t)(l * 2 + 1) * H_DIM * H_DIM;
        gemm_kernel<6, false><<<gemmGrid, 256>>>(hin, W0, zb, m,
                                                 N_NODES, H_DIM, H_DIM, H_DIM, 2 * H_DIM, 0);
        gemm_kernel<6, false><<<gemmGrid, 256>>>(hin, W1, zb, m,
                                                 N_NODES, H_DIM, H_DIM, H_DIM, 2 * H_DIM, H_DIM);
        aggregate_kernel<<<(N_NODES * 32 + 255) / 256, 256>>>(m, l, hout);
        float* t = hin; hin = hout; hout = t;
    }

    // decoder: out[:, :64] = hin @ dec_w + dec_b ; tail = final hidden h
    gemm_kernel<4, false><<<gemmGrid, 256>>>(hin, dec_w, dec_b, out,
                                             N_NODES, H_DIM, H_DIM, OUT_DIM, OUT_DIM, 0);
    copy_h_kernel<<<(N_NODES * H_DIM + 255) / 256, 256>>>(hin, out + (size_t)N_NODES * OUT_DIM);
    (void)in_sizes; (void)n_in; (void)out_size;
}

// round 2
// speedup vs baseline: 1.7727x; 1.7727x over previous
#include <cuda_runtime.h>

#define N_NODES 50000
#define E_EDGES 800000
#define IN_DIM  128
#define H_DIM   96
#define OUT_DIM 64
#define NUM_LAYERS 4
#define NB_SCAN ((N_NODES + 1023) / 1024)

// ---------------- static device scratch ----------------
__device__ float  g_h0[N_NODES * H_DIM];
__device__ float  g_h1[N_NODES * H_DIM];
__device__ float  g_agg[(size_t)N_NODES * 2 * H_DIM];      // [node][head*96+d]
__device__ int    g_counts[N_NODES];
__device__ int    g_offsets[N_NODES + 1];
__device__ int    g_cursor[N_NODES];
__device__ int    g_src_sorted[E_EDGES];
__device__ float2 g_ews[(size_t)E_EDGES * NUM_LAYERS];     // [pos][layer], 32B per edge
__device__ int    g_bsum[NB_SCAN + 1];
__device__ float  g_zero_bias[H_DIM];                      // static zeros

// ---------------- CSR build ----------------
__global__ void hist_kernel(const int* __restrict__ dst) {
    int e = blockIdx.x * blockDim.x + threadIdx.x;
    if (e < E_EDGES) atomicAdd(&g_counts[dst[e]], 1);
}

// phase 1: per-block exclusive scan of 1024 counts + block sum
__global__ void block_scan_kernel() {
    __shared__ int sh[1024];
    int t = threadIdx.x;
    int i = blockIdx.x * 1024 + t;
    int v = (i < N_NODES) ? g_counts[i] : 0;
    sh[t] = v;
    __syncthreads();
    #pragma unroll
    for (int off = 1; off < 1024; off <<= 1) {
        int x = (t >= off) ? sh[t - off] : 0;
        __syncthreads();
        sh[t] += x;
        __syncthreads();
    }
    if (i < N_NODES) g_offsets[i] = sh[t] - v;   // exclusive within block
    if (t == 1023) g_bsum[blockIdx.x] = sh[1023];
}

// phase 2: scan the 49 block sums (tiny)
__global__ void sums_scan_kernel() {
    __shared__ int sh[NB_SCAN];
    int t = threadIdx.x;
    if (t < NB_SCAN) sh[t] = g_bsum[t];
    __syncthreads();
    if (t == 0) {
        int run = 0;
        for (int i = 0; i < NB_SCAN; i++) { int v = sh[i]; g_bsum[i] = run; run += v; }
        g_bsum[NB_SCAN] = run;
    }
}

// phase 3: add block bases; init cursor
__global__ void add_base_kernel() {
    int i = blockIdx.x * blockDim.x + threadIdx.x;
    if (i < N_NODES) {
        int o = g_offsets[i] + g_bsum[i >> 10];
        g_offsets[i] = o;
        g_cursor[i] = o;
    }
    if (i == N_NODES) g_offsets[N_NODES] = g_bsum[NB_SCAN];
}

__global__ void scatter_kernel(const int* __restrict__ src,
                               const int* __restrict__ dst,
                               const float* __restrict__ conv_ew) {
    int e = blockIdx.x * blockDim.x + threadIdx.x;
    if (e >= E_EDGES) return;
    int d = dst[e];
    int pos = atomicAdd(&g_cursor[d], 1);
    g_src_sorted[pos] = src[e];
    #pragma unroll
    for (int l = 0; l < NUM_LAYERS; l++) {
        float w0 = conv_ew[(size_t)(l * 2 + 0) * E_EDGES + e];
        float w1 = conv_ew[(size_t)(l * 2 + 1) * E_EDGES + e];
        g_ews[(size_t)pos * NUM_LAYERS + l] = make_float2(w0, w1);  // 32B contiguous per edge
    }
}

// ---------------- register-tiled fp32 GEMM (BM=128, BN=TN*16, BK=16) ----------------
// Requires: K % 16 == 0, ldb == BN (B tile spans all columns), lda % 4 == 0.
template <int TN, bool RELU>
__global__ void gemm_kernel(const float* __restrict__ A, const float* __restrict__ B,
                            const float* __restrict__ bias, float* __restrict__ C,
                            int M, int K, int lda, int ldc) {
    constexpr int BN = TN * 16;
    constexpr int BM = 128;
    constexpr int BK = 16;
    constexpr int TM = 8;
    __shared__ float As[BK][BM + 4];
    __shared__ float Bs[BK][BN];

    int tid = threadIdx.x;
    int tx = tid & 15;
    int ty = tid >> 4;
    int blockRow = blockIdx.x * BM;

    float acc[TM][TN];
    #pragma unroll
    for (int i = 0; i < TM; i++)
        #pragma unroll
        for (int j = 0; j < TN; j++) acc[i][j] = 0.f;

    for (int k0 = 0; k0 < K; k0 += BK) {
        // A tile: 128x16 = 512 float4 loads, transpose into As[k][m]
        #pragma unroll
        for (int r = 0; r < 2; r++) {
            int f = tid + r * 256;
            int row = f >> 2;
            int seg = f & 3;
            int gRow = blockRow + row;
            float4 v = make_float4(0.f, 0.f, 0.f, 0.f);
            if (gRow < M) v = *(const float4*)(A + (size_t)gRow * lda + k0 + seg * 4);
            As[seg * 4 + 0][row] = v.x;
            As[seg * 4 + 1][row] = v.y;
            As[seg * 4 + 2][row] = v.z;
            As[seg * 4 + 3][row] = v.w;
        }
        // B tile: contiguous copy (ldb == BN)
        #pragma unroll
        for (int e = tid; e < BK * BN / 4; e += 256) {
            ((float4*)Bs)[e] = ((const float4*)(B + (size_t)k0 * BN))[e];
        }
        __syncthreads();
        #pragma unroll
        for (int kk = 0; kk < BK; kk++) {
            float a[TM], b[TN];
            float4 a0 = *(float4*)&As[kk][ty * TM];
            float4 a1 = *(float4*)&As[kk][ty * TM + 4];
            a[0] = a0.x; a[1] = a0.y; a[2] = a0.z; a[3] = a0.w;
            a[4] = a1.x; a[5] = a1.y; a[6] = a1.z; a[7] = a1.w;
            #pragma unroll
            for (int j = 0; j < TN / 2; j++) {
                float2 t2 = *(float2*)&Bs[kk][tx * TN + 2 * j];
                b[2 * j] = t2.x; b[2 * j + 1] = t2.y;
            }
            #pragma unroll
            for (int i = 0; i < TM; i++)
                #pragma unroll
                for (int j = 0; j < TN; j++) acc[i][j] += a[i] * b[j];
        }
        __syncthreads();
    }

    #pragma unroll
    for (int i = 0; i < TM; i++) {
        int gRow = blockRow + ty * TM + i;
        if (gRow >= M) continue;
        float* crow = C + (size_t)gRow * ldc + tx * TN;
        #pragma unroll
        for (int j = 0; j < TN / 2; j++) {
            float v0 = acc[i][2 * j + 0] + bias[tx * TN + 2 * j + 0];
            float v1 = acc[i][2 * j + 1] + bias[tx * TN + 2 * j + 1];
            if (RELU) { v0 = fmaxf(v0, 0.f); v1 = fmaxf(v1, 0.f); }
            *(float2*)(crow + 2 * j) = make_float2(v0, v1);
        }
    }
}

// ---------------- per-node aggregation of h (warp per node) ----------------
// agg[node][0:96]   = sum_e ew0[e] * h[src[e]]
// agg[node][96:192] = sum_e ew1[e] * h[src[e]]
__global__ void aggregate_kernel(const float* __restrict__ h, int layer,
                                 float* __restrict__ agg) {
    int warp = (blockIdx.x * blockDim.x + threadIdx.x) >> 5;
    int lane = threadIdx.x & 31;
    if (warp >= N_NODES) return;
    int beg = g_offsets[warp];
    int end = g_offsets[warp + 1];

    float a0 = 0.f, a1 = 0.f, a2 = 0.f;   // head 0
    float b0 = 0.f, b1 = 0.f, b2 = 0.f;   // head 1
    int j = beg;
    for (; j + 1 < end; j += 2) {
        int s0 = g_src_sorted[j];
        int s1 = g_src_sorted[j + 1];
        float2 w0 = g_ews[(size_t)j * NUM_LAYERS + layer];
        float2 w1 = g_ews[(size_t)(j + 1) * NUM_LAYERS + layer];
        const float* r0 = h + (size_t)s0 * H_DIM;
        const float* r1 = h + (size_t)s1 * H_DIM;
        float x0 = r0[lane], x1 = r0[32 + lane], x2 = r0[64 + lane];
        float y0 = r1[lane], y1 = r1[32 + lane], y2 = r1[64 + lane];
        a0 += w0.x * x0; a1 += w0.x * x1; a2 += w0.x * x2;
        b0 += w0.y * x0; b1 += w0.y * x1; b2 += w0.y * x2;
        a0 += w1.x * y0; a1 += w1.x * y1; a2 += w1.x * y2;
        b0 += w1.y * y0; b1 += w1.y * y1; b2 += w1.y * y2;
    }
    if (j < end) {
        int s = g_src_sorted[j];
        float2 w = g_ews[(size_t)j * NUM_LAYERS + layer];
        const float* r = h + (size_t)s * H_DIM;
        float x0 = r[lane], x1 = r[32 + lane], x2 = r[64 + lane];
        a0 += w.x * x0; a1 += w.x * x1; a2 += w.x * x2;
        b0 += w.y * x0; b1 += w.y * x1; b2 += w.y * x2;
    }
    float* o = agg + (size_t)warp * (2 * H_DIM);
    o[lane]       = a0; o[32 + lane]  = a1; o[64 + lane]  = a2;
    o[96 + lane]  = b0; o[128 + lane] = b1; o[160 + lane] = b2;
}

__global__ void copy_h_kernel(const float4* __restrict__ h, float4* __restrict__ out) {
    int i = blockIdx.x * blockDim.x + threadIdx.x;
    if (i < N_NODES * H_DIM / 4) out[i] = h[i];
}

// ---------------- launch ----------------
extern "C" void kernel_launch(void* const* d_in, const int* in_sizes, int n_in,
                              void* d_out, int out_size) {
    const float* x       = (const float*)d_in[0];
    const int*   eidx    = (const int*)d_in[1];
    const float* enc_w   = (const float*)d_in[2];
    const float* enc_b   = (const float*)d_in[3];
    const float* dec_w   = (const float*)d_in[4];
    const float* dec_b   = (const float*)d_in[5];
    const float* conv_W  = (const float*)d_in[6];
    const float* conv_ew = (const float*)d_in[7];
    float* out = (float*)d_out;

    const int* src = eidx;
    const int* dst = eidx + E_EDGES;

    void *p_h0, *p_h1, *p_agg, *p_zb, *p_counts;
    cudaGetSymbolAddress(&p_h0, g_h0);
    cudaGetSymbolAddress(&p_h1, g_h1);
    cudaGetSymbolAddress(&p_agg, g_agg);
    cudaGetSymbolAddress(&p_zb, g_zero_bias);
    cudaGetSymbolAddress(&p_counts, g_counts);
    float* h0 = (float*)p_h0;
    float* h1 = (float*)p_h1;
    float* agg = (float*)p_agg;
    const float* zb = (const float*)p_zb;

    // CSR build
    cudaMemsetAsync(p_counts, 0, N_NODES * sizeof(int));
    hist_kernel<<<(E_EDGES + 255) / 256, 256>>>(dst);
    block_scan_kernel<<<NB_SCAN, 1024>>>();
    sums_scan_kernel<<<1, 64>>>();
    add_base_kernel<<<(N_NODES + 256) / 256, 256>>>();
    scatter_kernel<<<(E_EDGES + 255) / 256, 256>>>(src, dst, conv_ew);

    int gemmGrid = (N_NODES + 127) / 128;

    // encoder: h0 = relu(x @ enc_w + enc_b)
    gemm_kernel<6, true><<<gemmGrid, 256>>>(x, enc_w, enc_b, h0,
                                            N_NODES, IN_DIM, IN_DIM, H_DIM);

    float* hin = h0;
    float* hout = h1;
    for (int l = 0; l < NUM_LAYERS; l++) {
        // aggregate first (linearity): agg = [Σ ew0*h[src], Σ ew1*h[src]]
        aggregate_kernel<<<(N_NODES * 32 + 255) / 256, 256>>>(hin, l, agg);
        // hout = relu(agg @ [W0; W1])  (K = 192, Wcat contiguous in conv_W)
        const float* Wcat = conv_W + (size_t)l * 2 * H_DIM * H_DIM;
        gemm_kernel<6, true><<<gemmGrid, 256>>>(agg, Wcat, zb, hout,
                                                N_NODES, 2 * H_DIM, 2 * H_DIM, H_DIM);
        float* t = hin; hin = hout; hout = t;
    }

    // decoder: out[:, :64] = hin @ dec_w + dec_b ; tail = final hidden
    gemm_kernel<4, false><<<gemmGrid, 256>>>(hin, dec_w, dec_b, out,
                                             N_NODES, H_DIM, H_DIM, OUT_DIM);
    copy_h_kernel<<<(N_NODES * H_DIM / 4 + 255) / 256, 256>>>(
        (const float4*)hin, (float4*)(out + (size_t)N_NODES * OUT_DIM));
    (void)in_sizes; (void)n_in; (void)out_size;
}

// round 4
// speedup vs baseline: 2.0429x; 1.1524x over previous
#include <cuda_runtime.h>
#include <cstdint>

#define N_NODES 50000
#define E_EDGES 800000
#define IN_DIM  128
#define H_DIM   96
#define OUT_DIM 64
#define NUM_LAYERS 4
#define NB_SCAN ((N_NODES + 1023) / 1024)

// ---------------- static device scratch ----------------
__device__ float  g_h0[N_NODES * H_DIM];
__device__ float  g_h1[N_NODES * H_DIM];
__device__ float  g_agg[(size_t)N_NODES * 2 * H_DIM];
__device__ int    g_counts[N_NODES];
__device__ int    g_offsets[N_NODES + 1];
__device__ int    g_cursor[N_NODES];
__device__ int    g_src_sorted[E_EDGES];
__device__ float2 g_ews[(size_t)E_EDGES * NUM_LAYERS];
__device__ int    g_bsum[NB_SCAN + 1];
__device__ float  g_zero_bias[H_DIM];

// ---------------- f32x2 packed helpers ----------------
__device__ __forceinline__ double pack2(float lo, float hi) {
    double d;
    asm("mov.b64 %0, {%1, %2};" : "=d"(d) : "f"(lo), "f"(hi));
    return d;
}
__device__ __forceinline__ void fma2(double& acc, double a, double b) {
    asm("fma.rn.f32x2 %0, %1, %2, %0;" : "+d"(acc) : "d"(a), "d"(b));
}
__device__ __forceinline__ float2 unpack2(double d) {
    float lo, hi;
    asm("mov.b64 {%0, %1}, %2;" : "=f"(lo), "=f"(hi) : "d"(d));
    return make_float2(lo, hi);
}

// ---------------- CSR build ----------------
__global__ void hist_kernel(const int* __restrict__ dst) {
    int e = blockIdx.x * blockDim.x + threadIdx.x;
    if (e < E_EDGES) atomicAdd(&g_counts[dst[e]], 1);
}

__global__ void block_scan_kernel() {
    __shared__ int sh[1024];
    int t = threadIdx.x;
    int i = blockIdx.x * 1024 + t;
    int v = (i < N_NODES) ? g_counts[i] : 0;
    sh[t] = v;
    __syncthreads();
    #pragma unroll
    for (int off = 1; off < 1024; off <<= 1) {
        int x = (t >= off) ? sh[t - off] : 0;
        __syncthreads();
        sh[t] += x;
        __syncthreads();
    }
    if (i < N_NODES) g_offsets[i] = sh[t] - v;
    if (t == 1023) g_bsum[blockIdx.x] = sh[1023];
}

__global__ void sums_scan_kernel() {
    if (threadIdx.x == 0) {
        int run = 0;
        for (int i = 0; i < NB_SCAN; i++) { int v = g_bsum[i]; g_bsum[i] = run; run += v; }
        g_bsum[NB_SCAN] = run;
    }
}

__global__ void add_base_kernel() {
    int i = blockIdx.x * blockDim.x + threadIdx.x;
    if (i < N_NODES) {
        int o = g_offsets[i] + g_bsum[i >> 10];
        g_offsets[i] = o;
        g_cursor[i] = o;
    }
    if (i == N_NODES) g_offsets[N_NODES] = g_bsum[NB_SCAN];
}

__global__ void scatter_kernel(const int* __restrict__ src,
                               const int* __restrict__ dst,
                               const float* __restrict__ conv_ew) {
    int e = blockIdx.x * blockDim.x + threadIdx.x;
    if (e >= E_EDGES) return;
    int d = dst[e];
    int pos = atomicAdd(&g_cursor[d], 1);
    g_src_sorted[pos] = src[e];
    #pragma unroll
    for (int l = 0; l < NUM_LAYERS; l++) {
        float w0 = conv_ew[(size_t)(l * 2 + 0) * E_EDGES + e];
        float w1 = conv_ew[(size_t)(l * 2 + 1) * E_EDGES + e];
        g_ews[(size_t)pos * NUM_LAYERS + l] = make_float2(w0, w1);
    }
}

// ---------------- register-tiled fp32 GEMM with packed f32x2 FMA ----------------
// BM=128, BN=TN*16, BK=16, per-thread 8(M) x TN(N); accumulators packed along M.
// Requires: K % 16 == 0, ldb == BN, lda % 4 == 0, TN even.
template <int TN, bool RELU>
__global__ void gemm_kernel(const float* __restrict__ A, const float* __restrict__ B,
                            const float* __restrict__ bias, float* __restrict__ C,
                            int M, int K, int lda, int ldc) {
    constexpr int BN = TN * 16;
    constexpr int BM = 128;
    constexpr int BK = 16;
    constexpr int TM = 8;
    __shared__ float As[BK][BM + 4];
    __shared__ float Bs[BK][BN];

    int tid = threadIdx.x;
    int tx = tid & 15;
    int ty = tid >> 4;
    int blockRow = blockIdx.x * BM;

    double acc[TM / 2][TN];   // acc[i2][j] = (row 2*i2, row 2*i2+1) for col j
    #pragma unroll
    for (int i = 0; i < TM / 2; i++)
        #pragma unroll
        for (int j = 0; j < TN; j++) acc[i][j] = 0.0;

    for (int k0 = 0; k0 < K; k0 += BK) {
        // A tile: 128x16, transpose into As[k][m]
        #pragma unroll
        for (int r = 0; r < 2; r++) {
            int f = tid + r * 256;
            int row = f >> 2;
            int seg = f & 3;
            int gRow = blockRow + row;
            float4 v = make_float4(0.f, 0.f, 0.f, 0.f);
            if (gRow < M) v = *(const float4*)(A + (size_t)gRow * lda + k0 + seg * 4);
            As[seg * 4 + 0][row] = v.x;
            As[seg * 4 + 1][row] = v.y;
            As[seg * 4 + 2][row] = v.z;
            As[seg * 4 + 3][row] = v.w;
        }
        // B tile: contiguous copy (ldb == BN)
        #pragma unroll
        for (int e = tid; e < BK * BN / 4; e += 256) {
            ((float4*)Bs)[e] = ((const float4*)(B + (size_t)k0 * BN))[e];
        }
        __syncthreads();
        #pragma unroll
        for (int kk = 0; kk < BK; kk++) {
            // A: 4 packed row-pairs via 64-bit LDS (m-contiguous)
            double a2[TM / 2];
            #pragma unroll
            for (int i = 0; i < TM / 2; i++)
                a2[i] = *(const double*)&As[kk][ty * TM + 2 * i];
            // B: TN scalars -> broadcast packs
            double b2[TN];
            #pragma unroll
            for (int j = 0; j < TN / 2; j++) {
                float2 t2 = *(const float2*)&Bs[kk][tx * TN + 2 * j];
                b2[2 * j + 0] = pack2(t2.x, t2.x);
                b2[2 * j + 1] = pack2(t2.y, t2.y);
            }
            #pragma unroll
            for (int i = 0; i < TM / 2; i++)
                #pragma unroll
                for (int j = 0; j < TN; j++) fma2(acc[i][j], a2[i], b2[j]);
        }
        __syncthreads();
    }

    #pragma unroll
    for (int i = 0; i < TM / 2; i++) {
        float2 col[TN];
        #pragma unroll
        for (int j = 0; j < TN; j++) col[j] = unpack2(acc[i][j]);
        #pragma unroll
        for (int half = 0; half < 2; half++) {
            int gRow = blockRow + ty * TM + 2 * i + half;
            if (gRow >= M) continue;
            float* crow = C + (size_t)gRow * ldc + tx * TN;
            #pragma unroll
            for (int j = 0; j < TN / 2; j++) {
                float v0 = (half ? col[2 * j + 0].y : col[2 * j + 0].x) + bias[tx * TN + 2 * j + 0];
                float v1 = (half ? col[2 * j + 1].y : col[2 * j + 1].x) + bias[tx * TN + 2 * j + 1];
                if (RELU) { v0 = fmaxf(v0, 0.f); v1 = fmaxf(v1, 0.f); }
                *(float2*)(crow + 2 * j) = make_float2(v0, v1);
            }
        }
    }
}

// ---------------- per-node aggregation (warp per node, 4-edge unroll) ----------------
__global__ void aggregate_kernel(const float* __restrict__ h, int layer,
                                 float* __restrict__ agg) {
    int warp = (blockIdx.x * blockDim.x + threadIdx.x) >> 5;
    int lane = threadIdx.x & 31;
    if (warp >= N_NODES) return;
    int beg = g_offsets[warp];
    int end = g_offsets[warp + 1];

    float a0 = 0.f, a1 = 0.f, a2 = 0.f;
    float b0 = 0.f, b1 = 0.f, b2 = 0.f;
    int j = beg;
    for (; j + 3 < end; j += 4) {
        int s0 = g_src_sorted[j], s1 = g_src_sorted[j + 1];
        int s2 = g_src_sorted[j + 2], s3 = g_src_sorted[j + 3];
        float2 w0 = g_ews[(size_t)j * NUM_LAYERS + layer];
        float2 w1 = g_ews[(size_t)(j + 1) * NUM_LAYERS + layer];
        float2 w2 = g_ews[(size_t)(j + 2) * NUM_LAYERS + layer];
        float2 w3 = g_ews[(size_t)(j + 3) * NUM_LAYERS + layer];
        const float* r0 = h + (size_t)s0 * H_DIM;
        const float* r1 = h + (size_t)s1 * H_DIM;
        const float* r2 = h + (size_t)s2 * H_DIM;
        const float* r3 = h + (size_t)s3 * H_DIM;
        float x00 = r0[lane], x01 = r0[32 + lane], x02 = r0[64 + lane];
        float x10 = r1[lane], x11 = r1[32 + lane], x12 = r1[64 + lane];
        float x20 = r2[lane], x21 = r2[32 + lane], x22 = r2[64 + lane];
        float x30 = r3[lane], x31 = r3[32 + lane], x32 = r3[64 + lane];
        a0 += w0.x * x00; a1 += w0.x * x01; a2 += w0.x * x02;
        b0 += w0.y * x00; b1 += w0.y * x01; b2 += w0.y * x02;
        a0 += w1.x * x10; a1 += w1.x * x11; a2 += w1.x * x12;
        b0 += w1.y * x10; b1 += w1.y * x11; b2 += w1.y * x12;
        a0 += w2.x * x20; a1 += w2.x * x21; a2 += w2.x * x22;
        b0 += w2.y * x20; b1 += w2.y * x21; b2 += w2.y * x22;
        a0 += w3.x * x30; a1 += w3.x * x31; a2 += w3.x * x32;
        b0 += w3.y * x30; b1 += w3.y * x31; b2 += w3.y * x32;
    }
    for (; j < end; j++) {
        int s = g_src_sorted[j];
        float2 w = g_ews[(size_t)j * NUM_LAYERS + layer];
        const float* r = h + (size_t)s * H_DIM;
        float x0 = r[lane], x1 = r[32 + lane], x2 = r[64 + lane];
        a0 += w.x * x0; a1 += w.x * x1; a2 += w.x * x2;
        b0 += w.y * x0; b1 += w.y * x1; b2 += w.y * x2;
    }
    float* o = agg + (size_t)warp * (2 * H_DIM);
    o[lane]       = a0; o[32 + lane]  = a1; o[64 + lane]  = a2;
    o[96 + lane]  = b0; o[128 + lane] = b1; o[160 + lane] = b2;
}

__global__ void copy_h_kernel(const float4* __restrict__ h, float4* __restrict__ out) {
    int i = blockIdx.x * blockDim.x + threadIdx.x;
    if (i < N_NODES * H_DIM / 4) out[i] = h[i];
}

// ---------------- launch ----------------
extern "C" void kernel_launch(void* const* d_in, const int* in_sizes, int n_in,
                              void* d_out, int out_size) {
    const float* x       = (const float*)d_in[0];
    const int*   eidx    = (const int*)d_in[1];
    const float* enc_w   = (const float*)d_in[2];
    const float* enc_b   = (const float*)d_in[3];
    const float* dec_w   = (const float*)d_in[4];
    const float* dec_b   = (const float*)d_in[5];
    const float* conv_W  = (const float*)d_in[6];
    const float* conv_ew = (const float*)d_in[7];
    float* out = (float*)d_out;

    const int* src = eidx;
    const int* dst = eidx + E_EDGES;

    void *p_h0, *p_h1, *p_agg, *p_zb, *p_counts;
    cudaGetSymbolAddress(&p_h0, g_h0);
    cudaGetSymbolAddress(&p_h1, g_h1);
    cudaGetSymbolAddress(&p_agg, g_agg);
    cudaGetSymbolAddress(&p_zb, g_zero_bias);
    cudaGetSymbolAddress(&p_counts, g_counts);
    float* h0 = (float*)p_h0;
    float* h1 = (float*)p_h1;
    float* agg = (float*)p_agg;
    const float* zb = (const float*)p_zb;

    // CSR build
    cudaMemsetAsync(p_counts, 0, N_NODES * sizeof(int));
    hist_kernel<<<(E_EDGES + 255) / 256, 256>>>(dst);
    block_scan_kernel<<<NB_SCAN, 1024>>>();
    sums_scan_kernel<<<1, 32>>>();
    add_base_kernel<<<(N_NODES + 256) / 256, 256>>>();
    scatter_kernel<<<(E_EDGES + 255) / 256, 256>>>(src, dst, conv_ew);

    int gemmGrid = (N_NODES + 127) / 128;

    // encoder: h0 = relu(x @ enc_w + enc_b)
    gemm_kernel<6, true><<<gemmGrid, 256>>>(x, enc_w, enc_b, h0,
                                            N_NODES, IN_DIM, IN_DIM, H_DIM);

    float* hin = h0;
    float* hout = h1;
    for (int l = 0; l < NUM_LAYERS; l++) {
        aggregate_kernel<<<(N_NODES * 32 + 255) / 256, 256>>>(hin, l, agg);
        const float* Wcat = conv_W + (size_t)l * 2 * H_DIM * H_DIM;
        gemm_kernel<6, true><<<gemmGrid, 256>>>(agg, Wcat, zb, hout,
                                                N_NODES, 2 * H_DIM, 2 * H_DIM, H_DIM);
        float* t = hin; hin = hout; hout = t;
    }

    // decoder + final hidden copy
    gemm_kernel<4, false><<<gemmGrid, 256>>>(hin, dec_w, dec_b, out,
                                             N_NODES, H_DIM, H_DIM, OUT_DIM);
    copy_h_kernel<<<(N_NODES * H_DIM / 4 + 255) / 256, 256>>>(
        (const float4*)hin, (float4*)(out + (size_t)N_NODES * OUT_DIM));
    (void)in_sizes; (void)n_in; (void)out_size;
}

// round 5
// speedup vs baseline: 2.1581x; 1.0564x over previous
#include <cuda_runtime.h>
#include <cuda_fp16.h>
#include <cstdint>

#define N_NODES 50000
#define E_EDGES 800000
#define IN_DIM  128
#define H_DIM   96
#define OUT_DIM 64
#define NUM_LAYERS 4
#define NB_SCAN ((N_NODES + 1023) / 1024)
#define HWORDS  48   // 96 channels as half2 words

// ---------------- static device scratch ----------------
__device__ float    g_h0[N_NODES * H_DIM];
__device__ float    g_h1[N_NODES * H_DIM];
__device__ uint32_t g_hhalf[(size_t)N_NODES * HWORDS];   // h as half2 words
__device__ float    g_agg[(size_t)N_NODES * 2 * H_DIM];
__device__ int      g_counts[N_NODES];
__device__ int      g_offsets[N_NODES + 1];
__device__ int      g_cursor[N_NODES];
__device__ int      g_src_sorted[E_EDGES];
__device__ float2   g_ews[(size_t)E_EDGES * NUM_LAYERS];
__device__ int      g_bsum[NB_SCAN + 1];
__device__ float    g_zero_bias[H_DIM];

// ---------------- f32x2 packed helpers ----------------
__device__ __forceinline__ double pack2(float lo, float hi) {
    double d;
    asm("mov.b64 %0, {%1, %2};" : "=d"(d) : "f"(lo), "f"(hi));
    return d;
}
__device__ __forceinline__ void fma2(double& acc, double a, double b) {
    asm("fma.rn.f32x2 %0, %1, %2, %0;" : "+d"(acc) : "d"(a), "d"(b));
}
__device__ __forceinline__ float2 unpack2(double d) {
    float lo, hi;
    asm("mov.b64 {%0, %1}, %2;" : "=f"(lo), "=f"(hi) : "d"(d));
    return make_float2(lo, hi);
}

// ---------------- CSR build ----------------
__global__ void hist_kernel(const int* __restrict__ dst) {
    int e = blockIdx.x * blockDim.x + threadIdx.x;
    if (e < E_EDGES) atomicAdd(&g_counts[dst[e]], 1);
}

__global__ void block_scan_kernel() {
    __shared__ int sh[1024];
    int t = threadIdx.x;
    int i = blockIdx.x * 1024 + t;
    int v = (i < N_NODES) ? g_counts[i] : 0;
    sh[t] = v;
    __syncthreads();
    #pragma unroll
    for (int off = 1; off < 1024; off <<= 1) {
        int x = (t >= off) ? sh[t - off] : 0;
        __syncthreads();
        sh[t] += x;
        __syncthreads();
    }
    if (i < N_NODES) g_offsets[i] = sh[t] - v;
    if (t == 1023) g_bsum[blockIdx.x] = sh[1023];
}

// add block bases (prefix over g_bsum computed redundantly per block)
__global__ void add_base_kernel() {
    __shared__ int pref[NB_SCAN + 1];
    if (threadIdx.x == 0) {
        int run = 0;
        #pragma unroll
        for (int i = 0; i < NB_SCAN; i++) { pref[i] = run; run += g_bsum[i]; }
        pref[NB_SCAN] = run;
    }
    __syncthreads();
    int i = blockIdx.x * blockDim.x + threadIdx.x;
    if (i < N_NODES) {
        int o = g_offsets[i] + pref[i >> 10];
        g_offsets[i] = o;
        g_cursor[i] = o;
    }
    if (i == N_NODES) g_offsets[N_NODES] = pref[NB_SCAN];
}

__global__ void scatter_kernel(const int* __restrict__ src,
                               const int* __restrict__ dst,
                               const float* __restrict__ conv_ew) {
    int e = blockIdx.x * blockDim.x + threadIdx.x;
    if (e >= E_EDGES) return;
    int d = dst[e];
    int pos = atomicAdd(&g_cursor[d], 1);
    g_src_sorted[pos] = src[e];
    #pragma unroll
    for (int l = 0; l < NUM_LAYERS; l++) {
        float w0 = conv_ew[(size_t)(l * 2 + 0) * E_EDGES + e];
        float w1 = conv_ew[(size_t)(l * 2 + 1) * E_EDGES + e];
        g_ews[(size_t)pos * NUM_LAYERS + l] = make_float2(w0, w1);
    }
}

// ---------------- register-tiled fp32 GEMM, packed f32x2 FMA ----------------
// BM=64, BN=TN*16, BK=16, 128 threads, per-thread 8(M) x TN(N).
// Optionally duplicates C to C2 (fp32) and emits half2-packed rows to Chalf (TN==6 only).
template <int TN, bool RELU>
__global__ void __launch_bounds__(128)
gemm_kernel(const float* __restrict__ A, const float* __restrict__ B,
            const float* __restrict__ bias, float* __restrict__ C,
            uint32_t* __restrict__ Chalf, float* __restrict__ C2,
            int M, int K, int lda, int ldc) {
    constexpr int BN = TN * 16;
    constexpr int BM = 64;
    constexpr int BK = 16;
    constexpr int TM = 8;
    __shared__ float As[BK][BM + 4];   // (BM+4)*4 = 272 B row stride, 8B-aligned
    __shared__ float Bs[BK][BN];

    int tid = threadIdx.x;
    int tx = tid & 15;
    int ty = tid >> 4;          // 0..7
    int blockRow = blockIdx.x * BM;

    double acc[TM / 2][TN];
    #pragma unroll
    for (int i = 0; i < TM / 2; i++)
        #pragma unroll
        for (int j = 0; j < TN; j++) acc[i][j] = 0.0;

    for (int k0 = 0; k0 < K; k0 += BK) {
        // A tile: 64x16 floats = 256 float4, 128 threads x 2
        #pragma unroll
        for (int r = 0; r < 2; r++) {
            int f = tid + r * 128;
            int row = f >> 2;
            int seg = f & 3;
            int gRow = blockRow + row;
            float4 v = make_float4(0.f, 0.f, 0.f, 0.f);
            if (gRow < M) v = *(const float4*)(A + (size_t)gRow * lda + k0 + seg * 4);
            As[seg * 4 + 0][row] = v.x;
            As[seg * 4 + 1][row] = v.y;
            As[seg * 4 + 2][row] = v.z;
            As[seg * 4 + 3][row] = v.w;
        }
        // B tile (ldb == BN): contiguous float4 copy
        #pragma unroll
        for (int e = tid; e < BK * BN / 4; e += 128)
            ((float4*)Bs)[e] = ((const float4*)(B + (size_t)k0 * BN))[e];
        __syncthreads();
        #pragma unroll
        for (int kk = 0; kk < BK; kk++) {
            double a2[TM / 2];
            #pragma unroll
            for (int i = 0; i < TM / 2; i++)
                a2[i] = *(const double*)&As[kk][ty * TM + 2 * i];
            double b2[TN];
            #pragma unroll
            for (int j = 0; j < TN / 2; j++) {
                float2 t2 = *(const float2*)&Bs[kk][tx * TN + 2 * j];
                b2[2 * j + 0] = pack2(t2.x, t2.x);
                b2[2 * j + 1] = pack2(t2.y, t2.y);
            }
            #pragma unroll
            for (int i = 0; i < TM / 2; i++)
                #pragma unroll
                for (int j = 0; j < TN; j++) fma2(acc[i][j], a2[i], b2[j]);
        }
        __syncthreads();
    }

    #pragma unroll
    for (int i = 0; i < TM / 2; i++) {
        float2 col[TN];
        #pragma unroll
        for (int j = 0; j < TN; j++) col[j] = unpack2(acc[i][j]);
        #pragma unroll
        for (int half = 0; half < 2; half++) {
            int gRow = blockRow + ty * TM + 2 * i + half;
            if (gRow >= M) continue;
            float v[TN];
            #pragma unroll
            for (int j = 0; j < TN; j++) {
                float t = (half ? col[j].y : col[j].x) + bias[tx * TN + j];
                v[j] = RELU ? fmaxf(t, 0.f) : t;
            }
            float* crow = C + (size_t)gRow * ldc + tx * TN;
            #pragma unroll
            for (int j = 0; j < TN / 2; j++)
                *(float2*)(crow + 2 * j) = make_float2(v[2 * j], v[2 * j + 1]);
            if (C2) {
                float* c2row = C2 + (size_t)gRow * ldc + tx * TN;
                #pragma unroll
                for (int j = 0; j < TN / 2; j++)
                    *(float2*)(c2row + 2 * j) = make_float2(v[2 * j], v[2 * j + 1]);
            }
            if (TN == 6 && Chalf) {
                uint32_t* hrow = Chalf + (size_t)gRow * HWORDS + tx * 3;
                #pragma unroll
                for (int j = 0; j < 3; j++) {
                    __half2 hv = __float22half2_rn(make_float2(v[2 * j], v[2 * j + 1]));
                    hrow[j] = *(uint32_t*)&hv;
                }
            }
        }
    }
}

// ---------------- per-node aggregation over fp16 h (warp per node) ----------------
// lane covers channels {2*lane, 2*lane+1}; lanes 0-15 additionally {64+2*lane, 65+2*lane}.
__global__ void aggregate_kernel(const uint32_t* __restrict__ hh, int layer,
                                 float* __restrict__ agg) {
    int warp = (blockIdx.x * blockDim.x + threadIdx.x) >> 5;
    int lane = threadIdx.x & 31;
    if (warp >= N_NODES) return;
    int beg = g_offsets[warp];
    int end = g_offsets[warp + 1];
    bool lo = lane < 16;

    float2 A0 = {0.f, 0.f}, B0 = {0.f, 0.f};   // head0/head1, channels 2l..2l+1
    float2 A1 = {0.f, 0.f}, B1 = {0.f, 0.f};   // channels 64+2l (lanes<16)
    int j = beg;
    for (; j + 3 < end; j += 4) {
        int s0 = g_src_sorted[j],     s1 = g_src_sorted[j + 1];
        int s2 = g_src_sorted[j + 2], s3 = g_src_sorted[j + 3];
        float2 w0 = g_ews[(size_t)j * NUM_LAYERS + layer];
        float2 w1 = g_ews[(size_t)(j + 1) * NUM_LAYERS + layer];
        float2 w2 = g_ews[(size_t)(j + 2) * NUM_LAYERS + layer];
        float2 w3 = g_ews[(size_t)(j + 3) * NUM_LAYERS + layer];
        const uint32_t* r0 = hh + (size_t)s0 * HWORDS;
        const uint32_t* r1 = hh + (size_t)s1 * HWORDS;
        const uint32_t* r2 = hh + (size_t)s2 * HWORDS;
        const uint32_t* r3 = hh + (size_t)s3 * HWORDS;
        uint32_t u00 = r0[lane], u10 = r1[lane], u20 = r2[lane], u30 = r3[lane];
        uint32_t u01 = lo ? r0[32 + lane] : 0;
        uint32_t u11 = lo ? r1[32 + lane] : 0;
        uint32_t u21 = lo ? r2[32 + lane] : 0;
        uint32_t u31 = lo ? r3[32 + lane] : 0;
        float2 x;
        x = __half22float2(*(__half2*)&u00);
        A0.x += w0.x * x.x; A0.y += w0.x * x.y; B0.x += w0.y * x.x; B0.y += w0.y * x.y;
        x = __half22float2(*(__half2*)&u10);
        A0.x += w1.x * x.x; A0.y += w1.x * x.y; B0.x += w1.y * x.x; B0.y += w1.y * x.y;
        x = __half22float2(*(__half2*)&u20);
        A0.x += w2.x * x.x; A0.y += w2.x * x.y; B0.x += w2.y * x.x; B0.y += w2.y * x.y;
        x = __half22float2(*(__half2*)&u30);
        A0.x += w3.x * x.x; A0.y += w3.x * x.y; B0.x += w3.y * x.x; B0.y += w3.y * x.y;
        x = __half22float2(*(__half2*)&u01);
        A1.x += w0.x * x.x; A1.y += w0.x * x.y; B1.x += w0.y * x.x; B1.y += w0.y * x.y;
        x = __half22float2(*(__half2*)&u11);
        A1.x += w1.x * x.x; A1.y += w1.x * x.y; B1.x += w1.y * x.x; B1.y += w1.y * x.y;
        x = __half22float2(*(__half2*)&u21);
        A1.x += w2.x * x.x; A1.y += w2.x * x.y; B1.x += w2.y * x.x; B1.y += w2.y * x.y;
        x = __half22float2(*(__half2*)&u31);
        A1.x += w3.x * x.x; A1.y += w3.x * x.y; B1.x += w3.y * x.x; B1.y += w3.y * x.y;
    }
    for (; j < end; j++) {
        int s = g_src_sorted[j];
        float2 w = g_ews[(size_t)j * NUM_LAYERS + layer];
        const uint32_t* r = hh + (size_t)s * HWORDS;
        uint32_t u0 = r[lane];
        uint32_t u1 = lo ? r[32 + lane] : 0;
        float2 x = __half22float2(*(__half2*)&u0);
        A0.x += w.x * x.x; A0.y += w.x * x.y; B0.x += w.y * x.x; B0.y += w.y * x.y;
        x = __half22float2(*(__half2*)&u1);
        A1.x += w.x * x.x; A1.y += w.x * x.y; B1.x += w.y * x.x; B1.y += w.y * x.y;
    }
    float* o = agg + (size_t)warp * (2 * H_DIM);
    *(float2*)(o + 2 * lane)       = A0;   // head0 ch 0..63
    *(float2*)(o + 96 + 2 * lane)  = B0;   // head1 ch 0..63
    if (lo) {
        *(float2*)(o + 64 + 2 * lane)  = A1;   // head0 ch 64..95
        *(float2*)(o + 160 + 2 * lane) = B1;   // head1 ch 64..95
    }
}

// ---------------- launch ----------------
extern "C" void kernel_launch(void* const* d_in, const int* in_sizes, int n_in,
                              void* d_out, int out_size) {
    const float* x       = (const float*)d_in[0];
    const int*   eidx    = (const int*)d_in[1];
    const float* enc_w   = (const float*)d_in[2];
    const float* enc_b   = (const float*)d_in[3];
    const float* dec_w   = (const float*)d_in[4];
    const float* dec_b   = (const float*)d_in[5];
    const float* conv_W  = (const float*)d_in[6];
    const float* conv_ew = (const float*)d_in[7];
    float* out = (float*)d_out;

    const int* src = eidx;
    const int* dst = eidx + E_EDGES;

    void *p_h0, *p_h1, *p_hh, *p_agg, *p_zb, *p_counts;
    cudaGetSymbolAddress(&p_h0, g_h0);
    cudaGetSymbolAddress(&p_h1, g_h1);
    cudaGetSymbolAddress(&p_hh, g_hhalf);
    cudaGetSymbolAddress(&p_agg, g_agg);
    cudaGetSymbolAddress(&p_zb, g_zero_bias);
    cudaGetSymbolAddress(&p_counts, g_counts);
    float* h0 = (float*)p_h0;
    float* h1 = (float*)p_h1;
    uint32_t* hh = (uint32_t*)p_hh;
    float* agg = (float*)p_agg;
    const float* zb = (const float*)p_zb;

    // CSR build
    cudaMemsetAsync(p_counts, 0, N_NODES * sizeof(int));
    hist_kernel<<<(E_EDGES + 255) / 256, 256>>>(dst);
    block_scan_kernel<<<NB_SCAN, 1024>>>();
    add_base_kernel<<<(N_NODES + 256) / 256, 256>>>();
    scatter_kernel<<<(E_EDGES + 255) / 256, 256>>>(src, dst, conv_ew);

    int gemmGrid = (N_NODES + 63) / 64;

    // encoder: h0 = relu(x @ enc_w + enc_b), also emit fp16 copy
    gemm_kernel<6, true><<<gemmGrid, 128>>>(x, enc_w, enc_b, h0, hh, nullptr,
                                            N_NODES, IN_DIM, IN_DIM, H_DIM);

    float* hin = h0;
    float* hout = h1;
    for (int l = 0; l < NUM_LAYERS; l++) {
        aggregate_kernel<<<(N_NODES * 32 + 255) / 256, 256>>>(hh, l, agg);
        const float* Wcat = conv_W + (size_t)l * 2 * H_DIM * H_DIM;
        uint32_t* hh_out = (l < NUM_LAYERS - 1) ? hh : nullptr;    // last layer: no fp16 needed
        float* c2 = (l == NUM_LAYERS - 1) ? (out + (size_t)N_NODES * OUT_DIM) : nullptr;
        gemm_kernel<6, true><<<gemmGrid, 128>>>(agg, Wcat, zb, hout, hh_out, c2,
                                                N_NODES, 2 * H_DIM, 2 * H_DIM, H_DIM);
        float* t = hin; hin = hout; hout = t;
    }

    // decoder: out[:, :64] = hin @ dec_w + dec_b
    gemm_kernel<4, false><<<gemmGrid, 128>>>(hin, dec_w, dec_b, out, nullptr, nullptr,
                                             N_NODES, H_DIM, H_DIM, OUT_DIM);
    (void)in_sizes; (void)n_in; (void)out_size;
}